// round 14
// baseline (speedup 1.0000x reference)
#include <cuda_runtime.h>
#include <cuda_bf16.h>
#include <cstdint>

#define NN 100000
#define NE 1000000

// ---------------- scratch (device globals) ----------------
__device__ float4 g_accA[NN * 16];
__device__ float4 g_accB[NN * 16];
__device__ float4 g_hw[NN * 16];
__device__ __nv_bfloat16 g_wbhi[3][128 * 128];  // weights hi, [j][k], row stride 128
__device__ __nv_bfloat16 g_wblo[3][128 * 128];  // weights lo
__device__ float g_wc[3][128 * 128];            // fp32 combined weights [k][j] (FMA fallback)
__device__ float g_bias[3][64];
__device__ int2 g_bucket[3][NE];
__device__ int g_cnt[3];

// ---------------- helpers ----------------
__device__ __forceinline__ uint32_t smem_u32(const void* p) {
    uint32_t a;
    asm("{ .reg .u64 t; cvta.to.shared.u64 t, %1; cvt.u32.u64 %0, t; }"
        : "=r"(a) : "l"(p));
    return a;
}
__device__ __forceinline__ unsigned long long pack2(float x, float y) {
    unsigned long long r;
    asm("mov.b64 %0, {%1,%2};" : "=l"(r) : "f"(x), "f"(y));
    return r;
}
__device__ __forceinline__ void fma2(unsigned long long& d, unsigned long long a,
                                     unsigned long long b) {
    asm("fma.rn.f32x2 %0, %1, %2, %0;" : "+l"(d) : "l"(a), "l"(b));
}
__device__ __forceinline__ float2 unpack2(unsigned long long v) {
    float2 r;
    asm("mov.b64 {%0,%1}, %2;" : "=f"(r.x), "=f"(r.y) : "l"(v));
    return r;
}

#if defined(__CUDA_ARCH__) && defined(__CUDA_ARCH_FEAT_SM103_ALL)
#define HAS_TCGEN05 1
#else
#define HAS_TCGEN05 0
#endif

#if HAS_TCGEN05
__device__ __forceinline__ uint32_t elect_one() {
    uint32_t pred;
    asm volatile(
        "{\n\t.reg .pred p;\n\telect.sync _|p, 0xFFFFFFFF;\n\t"
        "selp.b32 %0, 1, 0, p;\n\t}"
        : "=r"(pred));
    return pred;
}
#define TC_ALLOC(sa, n) \
    asm volatile("tcgen05.alloc.cta_group::1.sync.aligned.shared::cta.b32 [%0], %1;" \
                 ::"r"(sa), "r"((uint32_t)(n)) : "memory")
#define TC_RELINQ() \
    asm volatile("tcgen05.relinquish_alloc_permit.cta_group::1.sync.aligned;")
#define TC_DEALLOC(t, n) \
    asm volatile("tcgen05.dealloc.cta_group::1.sync.aligned.b32 %0, %1;" ::"r"(t), \
                 "r"((uint32_t)(n)))
#define TC_COMMIT(mb) \
    asm volatile( \
        "tcgen05.commit.cta_group::1.mbarrier::arrive::one.shared::cluster.b64 [%0];" \
        ::"r"(mb) : "memory")
#define TC_FENCE_AFTER() asm volatile("tcgen05.fence::after_thread_sync;" ::: "memory")
#define TC_FENCE_BEFORE() asm volatile("tcgen05.fence::before_thread_sync;" ::: "memory")
#define TC_WAIT_LD() asm volatile("tcgen05.wait::ld.sync.aligned;" ::: "memory")
#define FENCE_ASYNC_SHARED() asm volatile("fence.proxy.async.shared::cta;" ::: "memory")
#define MBAR_INIT(mb, c) \
    asm volatile("mbarrier.init.shared.b64 [%0], %1;" ::"r"(mb), "r"((uint32_t)(c)) \
                 : "memory")
#define MBAR_INVAL(mb) \
    asm volatile("mbarrier.inval.shared.b64 [%0];" ::"r"(mb) : "memory")

__device__ __forceinline__ void mbar_wait(uint32_t mb, uint32_t parity) {
    asm volatile(
        "{\n\t.reg .pred P1;\n\t"
        "WAIT_LOOP_%=:\n\t"
        "mbarrier.try_wait.parity.acquire.cta.shared::cta.b64 P1, [%0], %1, 0x989680;\n\t"
        "@P1 bra.uni WAIT_DONE_%=;\n\t"
        "bra.uni WAIT_LOOP_%=;\n\t"
        "WAIT_DONE_%=:\n\t}"
        ::"r"(mb), "r"(parity) : "memory");
}

#define TC_LD_X32(r, ta) \
    asm volatile( \
        "tcgen05.ld.sync.aligned.32x32b.x32.b32 " \
        "{%0, %1, %2, %3, %4, %5, %6, %7, " \
        " %8, %9, %10, %11, %12, %13, %14, %15, " \
        " %16, %17, %18, %19, %20, %21, %22, %23, " \
        " %24, %25, %26, %27, %28, %29, %30, %31}, [%32];" \
        : "=r"((r)[0]), "=r"((r)[1]), "=r"((r)[2]), "=r"((r)[3]), "=r"((r)[4]), \
          "=r"((r)[5]), "=r"((r)[6]), "=r"((r)[7]), "=r"((r)[8]), "=r"((r)[9]), \
          "=r"((r)[10]), "=r"((r)[11]), "=r"((r)[12]), "=r"((r)[13]), "=r"((r)[14]), \
          "=r"((r)[15]), "=r"((r)[16]), "=r"((r)[17]), "=r"((r)[18]), "=r"((r)[19]), \
          "=r"((r)[20]), "=r"((r)[21]), "=r"((r)[22]), "=r"((r)[23]), "=r"((r)[24]), \
          "=r"((r)[25]), "=r"((r)[26]), "=r"((r)[27]), "=r"((r)[28]), "=r"((r)[29]), \
          "=r"((r)[30]), "=r"((r)[31]) \
        : "r"(ta))

__device__ __forceinline__ void mma_f16_ss(uint32_t d, uint64_t a, uint64_t b,
                                           uint32_t idesc, bool acc) {
    uint32_t en = acc ? 1u : 0u;
    asm volatile(
        "{\n\t.reg .pred p;\n\tsetp.ne.u32 p, %5, 0;\n\t"
        "tcgen05.mma.cta_group::1.kind::f16 [%0], %1, %2, %3, {%4, %4, %4, %4}, p;\n\t}"
        ::"r"(d), "l"(a), "l"(b), "r"(idesc), "r"(0u), "r"(en)
        : "memory");
}

// SW128 K-major desc: layout=2, version=1, SBO=64, LBO=1
__device__ __forceinline__ uint64_t make_desc(uint32_t addr) {
    return ((uint64_t)2 << 61) | ((uint64_t)1 << 46) | ((uint64_t)64 << 32) |
           ((uint64_t)1 << 16) | ((uint64_t)(addr >> 4) & 0x3FFF);
}
#endif  // HAS_TCGEN05

#define SW128(b) ((b) ^ (((b) >> 3) & 0x70))

// ---------------- prep: bf16 hi/lo [j][k], fp32 [k][j], biases, counters
__global__ void prep_all_kernel(
    const float* __restrict__ wl0, const float* __restrict__ bl0,
    const float* __restrict__ w00, const float* __restrict__ b00,
    const float* __restrict__ w10, const float* __restrict__ b10,
    const float* __restrict__ wl1, const float* __restrict__ bl1,
    const float* __restrict__ w01, const float* __restrict__ b01,
    const float* __restrict__ w11, const float* __restrict__ b11,
    const float* __restrict__ wl2, const float* __restrict__ bl2,
    const float* __restrict__ w02, const float* __restrict__ b02,
    const float* __restrict__ w12, const float* __restrict__ b12) {
    int i = blockIdx.x * blockDim.x + threadIdx.x;  // 0..49151
    if (i < 3 * 16384) {
        int l = i >> 14;
        int idx = i & 16383;
        int j = idx >> 7;
        int k = idx & 127;
        int in_dim = (l == 0) ? 128 : 64;
        const float* wl = (l == 0) ? wl0 : (l == 1) ? wl1 : wl2;
        const float* w0 = (l == 0) ? w00 : (l == 1) ? w01 : w02;
        const float* w1 = (l == 0) ? w10 : (l == 1) ? w11 : w12;
        float v = 0.f;
        if (k < in_dim) {
            if (j < 64)
                v = wl[j * in_dim + k];
            else
                v = w0[(j - 64) * in_dim + k] + w1[(j - 64) * in_dim + k];
        }
        __nv_bfloat16 hi = __float2bfloat16_rn(v);
        __nv_bfloat16 lo = __float2bfloat16_rn(v - __bfloat162float(hi));
        g_wbhi[l][j * 128 + k] = hi;
        g_wblo[l][j * 128 + k] = lo;
        g_wc[l][k * 128 + j] = v;  // fp32 fallback layout [k][j]
    }
    if (blockIdx.x == 0 && threadIdx.x < 192) {
        int bl_ = threadIdx.x >> 6;
        int bj = threadIdx.x & 63;
        const float* pb = (bl_ == 0) ? bl0 : (bl_ == 1) ? bl1 : bl2;
        const float* p0 = (bl_ == 0) ? b00 : (bl_ == 1) ? b01 : b02;
        const float* p1 = (bl_ == 0) ? b10 : (bl_ == 1) ? b11 : b12;
        g_bias[bl_][bj] = pb[bj] + p0[bj] + p1[bj];
    }
    if (blockIdx.x == 1 && threadIdx.x < 3) g_cnt[threadIdx.x] = 0;
}

// ---------------- bucket: compact edges by relation
__global__ __launch_bounds__(256) void bucket_kernel(const int* __restrict__ ei,
                                                     const int* __restrict__ et) {
    __shared__ int s_cnt[3], s_base[3];
    int e = blockIdx.x * blockDim.x + threadIdx.x;
    if (threadIdx.x < 3) s_cnt[threadIdx.x] = 0;
    __syncthreads();
    int r = -1, local = 0;
    if (e < NE) {
        r = et[e];
        local = atomicAdd(&s_cnt[r], 1);
    }
    __syncthreads();
    if (threadIdx.x < 3)
        s_base[threadIdx.x] = atomicAdd(&g_cnt[threadIdx.x], s_cnt[threadIdx.x]);
    __syncthreads();
    if (e < NE) {
        int pos = s_base[r] + local;
        g_bucket[r][pos] = make_int2(ei[e], ei[NE + e]);
    }
}

// ---------------- GEMM: [hw | acc+bias] = h @ Wc^T
// 256 rows/CTA, 256 threads. Step order chunk-outer: (c0,h0),(c0,h1),(c1,h0),...
// so only ONE B chunk is smem-resident (66.5KB total -> 3 CTAs/SM all layers).
// tcgen05 split-bf16 on sm_103a; FMA fallback else.
template <int IN_DIM, bool RELU>
__global__ __launch_bounds__(256) void gemm_tc_kernel(const float* __restrict__ x,
                                                      int src_sel, int dst_sel,
                                                      int layer) {
    extern __shared__ __align__(1024) char smem[];
    const int tid = threadIdx.x;
    const int wid = tid >> 5;
    const int lane = tid & 31;
    const int m0 = blockIdx.x * 256;

    const float* __restrict__ h =
        (src_sel == 0) ? x
                       : (src_sel == 1) ? (const float*)g_accA : (const float*)g_accB;
    const float* __restrict__ bias = g_bias[layer];
    float4* __restrict__ accOut = dst_sel ? g_accB : g_accA;

#if HAS_TCGEN05
    // ======== tcgen05 path (sm_103a) ========
    const int CHUNKS = IN_DIM / 64;
    const int S = 2 * CHUNKS;
    const int A_HI = 1024, A_LO = 1024 + 16384;
    const int B_HI = 1024 + 32768, B_LO = 1024 + 49152;  // single chunk buffers
    const uint32_t sb = smem_u32(smem);
    const __nv_bfloat16* __restrict__ wh = g_wbhi[layer];
    const __nv_bfloat16* __restrict__ wlo = g_wblo[layer];

    // ---- B loader: one 64-col K-chunk (hi+lo), swizzled 16B stores ----
    auto loadB = [&](int c) {
#pragma unroll
        for (int t = 0; t < 4; t++) {
            int idx = t * 256 + tid;
            int r = idx >> 3;   // output col j 0..127
            int q = idx & 7;    // uint4 within 128B row
            uint32_t off = SW128((uint32_t)(r * 128 + q * 16));
            *(uint4*)(smem + B_HI + off) = *(const uint4*)(wh + r * 128 + c * 64 + q * 8);
            *(uint4*)(smem + B_LO + off) = *(const uint4*)(wlo + r * 128 + c * 64 + q * 8);
        }
    };
    // ---- A loader (128 rows x 64 fp32 -> bf16 hi/lo swizzled) ----
    auto loadA = [&](int half, int c) {
        const int k0 = c * 64;
        const int rbase = m0 + half * 128;
#pragma unroll
        for (int t = 0; t < 8; t++) {
            int idx = t * 256 + tid;
            int r = idx >> 4;
            int kq = idx & 15;
            int row = rbase + r;
            float4 v = make_float4(0.f, 0.f, 0.f, 0.f);
            if (row < NN) {
                v = *(const float4*)(h + (size_t)row * IN_DIM + k0 + kq * 4);
                if (RELU) {
                    v.x = fmaxf(v.x, 0.f);
                    v.y = fmaxf(v.y, 0.f);
                    v.z = fmaxf(v.z, 0.f);
                    v.w = fmaxf(v.w, 0.f);
                }
            }
            __nv_bfloat162 h0 = __float22bfloat162_rn(make_float2(v.x, v.y));
            __nv_bfloat162 h1 = __float22bfloat162_rn(make_float2(v.z, v.w));
            float2 f0 = __bfloat1622float2(h0);
            float2 f1 = __bfloat1622float2(h1);
            __nv_bfloat162 l0 =
                __float22bfloat162_rn(make_float2(v.x - f0.x, v.y - f0.y));
            __nv_bfloat162 l1 =
                __float22bfloat162_rn(make_float2(v.z - f1.x, v.w - f1.y));
            uint32_t off = SW128((uint32_t)(r * 128 + kq * 8));
            *(uint2*)(smem + A_HI + off) = make_uint2(*(uint32_t*)&h0, *(uint32_t*)&h1);
            *(uint2*)(smem + A_LO + off) = make_uint2(*(uint32_t*)&l0, *(uint32_t*)&l1);
        }
    };

    loadA(0, 0);
    loadB(0);
    if (wid == 0) {
        TC_ALLOC(sb + 0, 256);
        TC_RELINQ();
    }
    if (tid == 0) MBAR_INIT(sb + 8, 1);
    FENCE_ASYNC_SHARED();
    __syncthreads();
    uint32_t tmem;
    asm volatile("ld.shared.b32 %0, [%1];" : "=r"(tmem) : "r"(sb + 0));

    const uint32_t IDESC =
        (1u << 4) | (1u << 7) | (1u << 10) | (16u << 17) | (8u << 24);

    // ---- epilogue for one 128-row half (warps 0-3) ----
    auto epilogue = [&](int half) {
        if (wid >= 4) return;
        const int row = m0 + half * 128 + wid * 32 + lane;
        const uint32_t tbase = tmem + half * 128;
#pragma unroll
        for (int cb = 0; cb < 4; cb++) {
            uint32_t r[32];
            TC_LD_X32(r, tbase + cb * 32);
            TC_WAIT_LD();
            if (row < NN) {
#pragma unroll
                for (int t = 0; t < 8; t++) {
                    float4 v = make_float4(
                        __uint_as_float(r[4 * t + 0]), __uint_as_float(r[4 * t + 1]),
                        __uint_as_float(r[4 * t + 2]), __uint_as_float(r[4 * t + 3]));
                    int j4 = cb * 8 + t;
                    if (j4 < 16) {
                        g_hw[row * 16 + j4] = v;
                    } else {
                        int jj = (j4 - 16) * 4;
                        v.x += bias[jj + 0];
                        v.y += bias[jj + 1];
                        v.z += bias[jj + 2];
                        v.w += bias[jj + 3];
                        accOut[row * 16 + (j4 - 16)] = v;
                    }
                }
            }
        }
    };

    // steps: s -> (c = s/2, half = s&1). D(half) accumulates across c.
#pragma unroll
    for (int s = 0; s < S; s++) {
        const int c = s >> 1;
        const int hh = s & 1;
        if (s > 0) {
            // wait for previous MMA set before overwriting A (and B) tiles
            mbar_wait(sb + 8, (uint32_t)((s - 1) & 1));
            loadA(hh, c);
            if (hh == 0) loadB(c);
            FENCE_ASYNC_SHARED();
            __syncthreads();
        }
        if (wid == 0 && elect_one()) {
            uint64_t ah = make_desc(sb + A_HI), al = make_desc(sb + A_LO);
            uint64_t bh = make_desc(sb + B_HI), bl = make_desc(sb + B_LO);
            uint32_t d = tmem + hh * 128;
#pragma unroll
            for (int st = 0; st < 4; st++)
                mma_f16_ss(d, ah + 2 * st, bh + 2 * st, IDESC, !(c == 0 && st == 0));
#pragma unroll
            for (int st = 0; st < 4; st++)
                mma_f16_ss(d, ah + 2 * st, bl + 2 * st, IDESC, true);
#pragma unroll
            for (int st = 0; st < 4; st++)
                mma_f16_ss(d, al + 2 * st, bh + 2 * st, IDESC, true);
            TC_COMMIT(sb + 8);
        }
        if (s == S - 1) {
            // D0 complete (commit S-2 waited at top of this iter);
            // overlap its epilogue with the final D1 MMA.
            TC_FENCE_AFTER();
            epilogue(0);
        }
    }
    mbar_wait(sb + 8, (uint32_t)((S - 1) & 1));
    TC_FENCE_AFTER();
    epilogue(1);
    TC_FENCE_BEFORE();
    __syncthreads();
    if (tid == 0) MBAR_INVAL(sb + 8);
    if (wid == 0) TC_DEALLOC(tmem, 256);

#else
    // ======== FMA fallback (plain sm_103 target) — round-5 proven path ========
    float* a_s = (float*)smem;                    // [32][68]
    float4* b_s = (float4*)(smem + 32 * 68 * 4);  // [32][32]
    const float4* wc4 = (const float4*)g_wc[layer];
    const int ty = wid;

    for (int half = 0; half < 4; half++) {
        const int hm0 = m0 + half * 64;
        unsigned long long acc[8][2];
#pragma unroll
        for (int i = 0; i < 8; i++) { acc[i][0] = 0ull; acc[i][1] = 0ull; }

        for (int k0 = 0; k0 < IN_DIM; k0 += 32) {
#pragma unroll
            for (int t = 0; t < 2; t++) {
                int idx = t * 256 + tid;
                int r = idx >> 3;
                int kq = idx & 7;
                int row = hm0 + r;
                float4 v = make_float4(0.f, 0.f, 0.f, 0.f);
                if (row < NN) {
                    v = *(const float4*)(h + (size_t)row * IN_DIM + k0 + kq * 4);
                    if (RELU) {
                        v.x = fmaxf(v.x, 0.f);
                        v.y = fmaxf(v.y, 0.f);
                        v.z = fmaxf(v.z, 0.f);
                        v.w = fmaxf(v.w, 0.f);
                    }
                }
                a_s[(kq * 4 + 0) * 68 + r] = v.x;
                a_s[(kq * 4 + 1) * 68 + r] = v.y;
                a_s[(kq * 4 + 2) * 68 + r] = v.z;
                a_s[(kq * 4 + 3) * 68 + r] = v.w;
            }
#pragma unroll
            for (int t = 0; t < 4; t++) {
                int idx = t * 256 + tid;
                b_s[idx] = wc4[(size_t)(k0 + (idx >> 5)) * 32 + (idx & 31)];
            }
            __syncthreads();

#pragma unroll
            for (int k = 0; k < 32; k++) {
                float4 b4 = b_s[k * 32 + lane];
                unsigned long long b01 = pack2(b4.x, b4.y);
                unsigned long long b23 = pack2(b4.z, b4.w);
                float4 a0 = *(const float4*)&a_s[k * 68 + ty * 8];
                float4 a1 = *(const float4*)&a_s[k * 68 + ty * 8 + 4];
                unsigned long long a2;
                a2 = pack2(a0.x, a0.x); fma2(acc[0][0], a2, b01); fma2(acc[0][1], a2, b23);
                a2 = pack2(a0.y, a0.y); fma2(acc[1][0], a2, b01); fma2(acc[1][1], a2, b23);
                a2 = pack2(a0.z, a0.z); fma2(acc[2][0], a2, b01); fma2(acc[2][1], a2, b23);
                a2 = pack2(a0.w, a0.w); fma2(acc[3][0], a2, b01); fma2(acc[3][1], a2, b23);
                a2 = pack2(a1.x, a1.x); fma2(acc[4][0], a2, b01); fma2(acc[4][1], a2, b23);
                a2 = pack2(a1.y, a1.y); fma2(acc[5][0], a2, b01); fma2(acc[5][1], a2, b23);
                a2 = pack2(a1.z, a1.z); fma2(acc[6][0], a2, b01); fma2(acc[6][1], a2, b23);
                a2 = pack2(a1.w, a1.w); fma2(acc[7][0], a2, b01); fma2(acc[7][1], a2, b23);
            }
            __syncthreads();
        }

#pragma unroll
        for (int i = 0; i < 8; i++) {
            int row = hm0 + ty * 8 + i;
            if (row < NN) {
                float2 lo = unpack2(acc[i][0]);
                float2 hi = unpack2(acc[i][1]);
                float4 v = make_float4(lo.x, lo.y, hi.x, hi.y);
                if (lane < 16) {
                    g_hw[row * 16 + lane] = v;
                } else {
                    int jj = (lane - 16) * 4;
                    v.x += bias[jj + 0];
                    v.y += bias[jj + 1];
                    v.z += bias[jj + 2];
                    v.w += bias[jj + 3];
                    accOut[row * 16 + (lane - 16)] = v;
                }
            }
        }
        __syncthreads();
    }
#endif
}

// ---------------- scatter: acc[src] += hw[dst] over compacted bucket
// thread-per-(edge,chunk), batched grid-stride unroll-4 (round-9/11 proven)
__global__ __launch_bounds__(256) void scatter_kernel(int rel, int dst_sel) {
    float4* __restrict__ acc = dst_sel ? g_accB : g_accA;
    const int2* __restrict__ bk = g_bucket[rel];
    const int n16 = g_cnt[rel] << 4;
    const int T = gridDim.x * blockDim.x;
    int id0 = blockIdx.x * blockDim.x + threadIdx.x;
    for (int base = id0; base < n16; base += 4 * T) {
        int ids[4];
        int2 p[4];
        bool ok[4];
#pragma unroll
        for (int u = 0; u < 4; u++) {
            ids[u] = base + u * T;
            ok[u] = ids[u] < n16;
            p[u] = ok[u] ? bk[ids[u] >> 4] : make_int2(0, 0);
        }
        float4 v[4];
#pragma unroll
        for (int u = 0; u < 4; u++)
            v[u] = ok[u] ? g_hw[p[u].y * 16 + (ids[u] & 15)]
                         : make_float4(0.f, 0.f, 0.f, 0.f);
#pragma unroll
        for (int u = 0; u < 4; u++) {
            if (ok[u]) {
                float* dp = (float*)acc + (size_t)p[u].x * 64 + (ids[u] & 15) * 4;
                asm volatile("red.global.add.v4.f32 [%0], {%1,%2,%3,%4};" ::"l"(dp),
                             "f"(v[u].x), "f"(v[u].y), "f"(v[u].z), "f"(v[u].w)
                             : "memory");
            }
        }
    }
}

// ---------------- final relu
__global__ __launch_bounds__(256) void relu_kernel(float* __restrict__ out) {
    int i = blockIdx.x * blockDim.x + threadIdx.x;
    if (i < NN * 16) {
        float4 v = g_accA[i];
        v.x = fmaxf(v.x, 0.f);
        v.y = fmaxf(v.y, 0.f);
        v.z = fmaxf(v.z, 0.f);
        v.w = fmaxf(v.w, 0.f);
        ((float4*)out)[i] = v;
    }
}

extern "C" void kernel_launch(void* const* d_in, const int* in_sizes, int n_in,
                              void* d_out, int out_size) {
    const float* x = (const float*)d_in[0];
    const int* ei = (const int*)d_in[1];
    const int* et = (const int*)d_in[2];
    float* out = (float*)d_out;

    const float* W[18];
    for (int i = 0; i < 18; i++) W[i] = (const float*)d_in[3 + i];

    const int SMEM_TOTAL = 1024 + 32768 + 32768;  // 66560 — 3 CTAs/SM all layers
    cudaFuncSetAttribute(gemm_tc_kernel<128, false>,
                         cudaFuncAttributeMaxDynamicSharedMemorySize, SMEM_TOTAL);
    cudaFuncSetAttribute(gemm_tc_kernel<64, true>,
                         cudaFuncAttributeMaxDynamicSharedMemorySize, SMEM_TOTAL);

    const int GEMM_GRID = (NN + 255) / 256;  // 391
    const int SCAT_GRID = 2048;
    const int RELU_GRID = (NN * 16 + 255) / 256;
    const int BUCK_GRID = (NE + 255) / 256;

    prep_all_kernel<<<192, 256>>>(W[0], W[1], W[2], W[3], W[4], W[5], W[6], W[7],
                                  W[8], W[9], W[10], W[11], W[12], W[13], W[14],
                                  W[15], W[16], W[17]);
    bucket_kernel<<<BUCK_GRID, 256>>>(ei, et);

    // Layer 0: x -> accA
    gemm_tc_kernel<128, false><<<GEMM_GRID, 256, SMEM_TOTAL>>>(x, 0, 0, 0);
    scatter_kernel<<<SCAT_GRID, 256>>>(0, 0);
    // Layer 1: relu(accA) -> accB
    gemm_tc_kernel<64, true><<<GEMM_GRID, 256, SMEM_TOTAL>>>(x, 1, 1, 1);
    scatter_kernel<<<SCAT_GRID, 256>>>(1, 1);
    // Layer 2: relu(accB) -> accA
    gemm_tc_kernel<64, true><<<GEMM_GRID, 256, SMEM_TOTAL>>>(x, 2, 0, 2);
    scatter_kernel<<<SCAT_GRID, 256>>>(2, 0);

    relu_kernel<<<RELU_GRID, 256>>>(out);
}

// round 15
// speedup vs baseline: 1.0757x; 1.0757x over previous
#include <cuda_runtime.h>
#include <cuda_bf16.h>
#include <cstdint>

#define NN 100000
#define NE 1000000

// ---------------- scratch (device globals) ----------------
__device__ float4 g_accA[NN * 16];
__device__ float4 g_accB[NN * 16];
__device__ float4 g_hw[NN * 16];
__device__ __nv_bfloat16 g_wbhi[3][128 * 128];  // weights hi, [j][k], row stride 128
__device__ __nv_bfloat16 g_wblo[3][128 * 128];  // weights lo
__device__ float g_wc[3][128 * 128];            // fp32 combined weights [k][j] (FMA fallback)
__device__ float g_bias[3][64];
__device__ int2 g_bucket[3][NE];
__device__ int g_cnt[3];  // zero-init at load; relu_kernel re-zeroes at end of every launch

// ---------------- helpers ----------------
__device__ __forceinline__ uint32_t smem_u32(const void* p) {
    uint32_t a;
    asm("{ .reg .u64 t; cvta.to.shared.u64 t, %1; cvt.u32.u64 %0, t; }"
        : "=r"(a) : "l"(p));
    return a;
}
__device__ __forceinline__ unsigned long long pack2(float x, float y) {
    unsigned long long r;
    asm("mov.b64 %0, {%1,%2};" : "=l"(r) : "f"(x), "f"(y));
    return r;
}
__device__ __forceinline__ void fma2(unsigned long long& d, unsigned long long a,
                                     unsigned long long b) {
    asm("fma.rn.f32x2 %0, %1, %2, %0;" : "+l"(d) : "l"(a), "l"(b));
}
__device__ __forceinline__ float2 unpack2(unsigned long long v) {
    float2 r;
    asm("mov.b64 {%0,%1}, %2;" : "=f"(r.x), "=f"(r.y) : "l"(v));
    return r;
}

#if defined(__CUDA_ARCH__) && defined(__CUDA_ARCH_FEAT_SM103_ALL)
#define HAS_TCGEN05 1
#else
#define HAS_TCGEN05 0
#endif

#if HAS_TCGEN05
__device__ __forceinline__ uint32_t elect_one() {
    uint32_t pred;
    asm volatile(
        "{\n\t.reg .pred p;\n\telect.sync _|p, 0xFFFFFFFF;\n\t"
        "selp.b32 %0, 1, 0, p;\n\t}"
        : "=r"(pred));
    return pred;
}
#define TC_ALLOC(sa, n) \
    asm volatile("tcgen05.alloc.cta_group::1.sync.aligned.shared::cta.b32 [%0], %1;" \
                 ::"r"(sa), "r"((uint32_t)(n)) : "memory")
#define TC_RELINQ() \
    asm volatile("tcgen05.relinquish_alloc_permit.cta_group::1.sync.aligned;")
#define TC_DEALLOC(t, n) \
    asm volatile("tcgen05.dealloc.cta_group::1.sync.aligned.b32 %0, %1;" ::"r"(t), \
                 "r"((uint32_t)(n)))
#define TC_COMMIT(mb) \
    asm volatile( \
        "tcgen05.commit.cta_group::1.mbarrier::arrive::one.shared::cluster.b64 [%0];" \
        ::"r"(mb) : "memory")
#define TC_FENCE_AFTER() asm volatile("tcgen05.fence::after_thread_sync;" ::: "memory")
#define TC_FENCE_BEFORE() asm volatile("tcgen05.fence::before_thread_sync;" ::: "memory")
#define TC_WAIT_LD() asm volatile("tcgen05.wait::ld.sync.aligned;" ::: "memory")
#define FENCE_ASYNC_SHARED() asm volatile("fence.proxy.async.shared::cta;" ::: "memory")
#define MBAR_INIT(mb, c) \
    asm volatile("mbarrier.init.shared.b64 [%0], %1;" ::"r"(mb), "r"((uint32_t)(c)) \
                 : "memory")
#define MBAR_INVAL(mb) \
    asm volatile("mbarrier.inval.shared.b64 [%0];" ::"r"(mb) : "memory")

__device__ __forceinline__ void mbar_wait(uint32_t mb, uint32_t parity) {
    asm volatile(
        "{\n\t.reg .pred P1;\n\t"
        "WAIT_LOOP_%=:\n\t"
        "mbarrier.try_wait.parity.acquire.cta.shared::cta.b64 P1, [%0], %1, 0x989680;\n\t"
        "@P1 bra.uni WAIT_DONE_%=;\n\t"
        "bra.uni WAIT_LOOP_%=;\n\t"
        "WAIT_DONE_%=:\n\t}"
        ::"r"(mb), "r"(parity) : "memory");
}

#define TC_LD_X32(r, ta) \
    asm volatile( \
        "tcgen05.ld.sync.aligned.32x32b.x32.b32 " \
        "{%0, %1, %2, %3, %4, %5, %6, %7, " \
        " %8, %9, %10, %11, %12, %13, %14, %15, " \
        " %16, %17, %18, %19, %20, %21, %22, %23, " \
        " %24, %25, %26, %27, %28, %29, %30, %31}, [%32];" \
        : "=r"((r)[0]), "=r"((r)[1]), "=r"((r)[2]), "=r"((r)[3]), "=r"((r)[4]), \
          "=r"((r)[5]), "=r"((r)[6]), "=r"((r)[7]), "=r"((r)[8]), "=r"((r)[9]), \
          "=r"((r)[10]), "=r"((r)[11]), "=r"((r)[12]), "=r"((r)[13]), "=r"((r)[14]), \
          "=r"((r)[15]), "=r"((r)[16]), "=r"((r)[17]), "=r"((r)[18]), "=r"((r)[19]), \
          "=r"((r)[20]), "=r"((r)[21]), "=r"((r)[22]), "=r"((r)[23]), "=r"((r)[24]), \
          "=r"((r)[25]), "=r"((r)[26]), "=r"((r)[27]), "=r"((r)[28]), "=r"((r)[29]), \
          "=r"((r)[30]), "=r"((r)[31]) \
        : "r"(ta))

__device__ __forceinline__ void mma_f16_ss(uint32_t d, uint64_t a, uint64_t b,
                                           uint32_t idesc, bool acc) {
    uint32_t en = acc ? 1u : 0u;
    asm volatile(
        "{\n\t.reg .pred p;\n\tsetp.ne.u32 p, %5, 0;\n\t"
        "tcgen05.mma.cta_group::1.kind::f16 [%0], %1, %2, %3, {%4, %4, %4, %4}, p;\n\t}"
        ::"r"(d), "l"(a), "l"(b), "r"(idesc), "r"(0u), "r"(en)
        : "memory");
}

// SW128 K-major desc: layout=2, version=1, SBO=64, LBO=1
__device__ __forceinline__ uint64_t make_desc(uint32_t addr) {
    return ((uint64_t)2 << 61) | ((uint64_t)1 << 46) | ((uint64_t)64 << 32) |
           ((uint64_t)1 << 16) | ((uint64_t)(addr >> 4) & 0x3FFF);
}
#endif  // HAS_TCGEN05

#define SW128(b) ((b) ^ (((b) >> 3) & 0x70))

// ---------------- merged prep + bucket (g_cnt is pre-zeroed: load-time init
// on the first launch, relu_kernel end-reset on every subsequent launch)
// blocks [0,192): weight prep. blocks [192, 192+BUCK): edge bucketing.
__global__ __launch_bounds__(256) void prep_bucket_kernel(
    const int* __restrict__ ei, const int* __restrict__ et,
    const float* __restrict__ wl0, const float* __restrict__ bl0,
    const float* __restrict__ w00, const float* __restrict__ b00,
    const float* __restrict__ w10, const float* __restrict__ b10,
    const float* __restrict__ wl1, const float* __restrict__ bl1,
    const float* __restrict__ w01, const float* __restrict__ b01,
    const float* __restrict__ w11, const float* __restrict__ b11,
    const float* __restrict__ wl2, const float* __restrict__ bl2,
    const float* __restrict__ w02, const float* __restrict__ b02,
    const float* __restrict__ w12, const float* __restrict__ b12) {
    if (blockIdx.x < 192) {
        int i = blockIdx.x * blockDim.x + threadIdx.x;  // 0..49151
        if (i < 3 * 16384) {
            int l = i >> 14;
            int idx = i & 16383;
            int j = idx >> 7;
            int k = idx & 127;
            int in_dim = (l == 0) ? 128 : 64;
            const float* wl = (l == 0) ? wl0 : (l == 1) ? wl1 : wl2;
            const float* w0 = (l == 0) ? w00 : (l == 1) ? w01 : w02;
            const float* w1 = (l == 0) ? w10 : (l == 1) ? w11 : w12;
            float v = 0.f;
            if (k < in_dim) {
                if (j < 64)
                    v = wl[j * in_dim + k];
                else
                    v = w0[(j - 64) * in_dim + k] + w1[(j - 64) * in_dim + k];
            }
            __nv_bfloat16 hi = __float2bfloat16_rn(v);
            __nv_bfloat16 lo = __float2bfloat16_rn(v - __bfloat162float(hi));
            g_wbhi[l][j * 128 + k] = hi;
            g_wblo[l][j * 128 + k] = lo;
            g_wc[l][k * 128 + j] = v;  // fp32 fallback layout [k][j]
        }
        if (blockIdx.x == 0 && threadIdx.x < 192) {
            int bl_ = threadIdx.x >> 6;
            int bj = threadIdx.x & 63;
            const float* pb = (bl_ == 0) ? bl0 : (bl_ == 1) ? bl1 : bl2;
            const float* p0 = (bl_ == 0) ? b00 : (bl_ == 1) ? b01 : b02;
            const float* p1 = (bl_ == 0) ? b10 : (bl_ == 1) ? b11 : b12;
            g_bias[bl_][bj] = pb[bj] + p0[bj] + p1[bj];
        }
    } else {
        __shared__ int s_cnt[3], s_base[3];
        int e = (blockIdx.x - 192) * blockDim.x + threadIdx.x;
        if (threadIdx.x < 3) s_cnt[threadIdx.x] = 0;
        __syncthreads();
        int r = -1, local = 0;
        if (e < NE) {
            r = et[e];
            local = atomicAdd(&s_cnt[r], 1);
        }
        __syncthreads();
        if (threadIdx.x < 3)
            s_base[threadIdx.x] = atomicAdd(&g_cnt[threadIdx.x], s_cnt[threadIdx.x]);
        __syncthreads();
        if (e < NE) {
            int pos = s_base[r] + local;
            g_bucket[r][pos] = make_int2(ei[e], ei[NE + e]);
        }
    }
}

// ---------------- GEMM: [hw | acc+bias] = h @ Wc^T
// 256 rows/CTA (two 128-row halves sharing B tiles), 256 threads.
// tcgen05 split-bf16 on sm_103a (R11 proven form); FMA fallback else.
template <int IN_DIM, bool RELU>
__global__ __launch_bounds__(256) void gemm_tc_kernel(const float* __restrict__ x,
                                                      int src_sel, int dst_sel,
                                                      int layer) {
    extern __shared__ __align__(1024) char smem[];
    const int tid = threadIdx.x;
    const int wid = tid >> 5;
    const int lane = tid & 31;
    const int m0 = blockIdx.x * 256;

    const float* __restrict__ h =
        (src_sel == 0) ? x
                       : (src_sel == 1) ? (const float*)g_accA : (const float*)g_accB;
    const float* __restrict__ bias = g_bias[layer];
    float4* __restrict__ accOut = dst_sel ? g_accB : g_accA;

#if HAS_TCGEN05
    // ======== tcgen05 path (sm_103a) ========
    const int CHUNKS = IN_DIM / 64;
    const int A_HI = 1024, A_LO = 1024 + 16384;
    const int B_HI = 1024 + 32768;
    const int B_LO = B_HI + CHUNKS * 16384;
    const uint32_t sb = smem_u32(smem);
    const __nv_bfloat16* __restrict__ wh = g_wbhi[layer];
    const __nv_bfloat16* __restrict__ wlo = g_wblo[layer];

    // ---- load all B chunks (hi+lo) once per CTA ----
#pragma unroll
    for (int t = 0; t < 4 * CHUNKS; t++) {
        int idx = t * 256 + tid;
        int c = idx >> 10;             // chunk
        int r = (idx >> 3) & 127;      // output col j
        int q = idx & 7;               // uint4 within 128B row
        uint32_t off = c * 16384 + SW128((uint32_t)(r * 128 + q * 16));
        *(uint4*)(smem + B_HI + off) = *(const uint4*)(wh + r * 128 + c * 64 + q * 8);
        *(uint4*)(smem + B_LO + off) = *(const uint4*)(wlo + r * 128 + c * 64 + q * 8);
    }

    // ---- A loader (128 rows x 64 fp32 -> bf16 hi/lo swizzled) ----
    auto loadA = [&](int half, int c) {
        const int k0 = c * 64;
        const int rbase = m0 + half * 128;
#pragma unroll
        for (int t = 0; t < 8; t++) {
            int idx = t * 256 + tid;
            int r = idx >> 4;
            int kq = idx & 15;
            int row = rbase + r;
            float4 v = make_float4(0.f, 0.f, 0.f, 0.f);
            if (row < NN) {
                v = *(const float4*)(h + (size_t)row * IN_DIM + k0 + kq * 4);
                if (RELU) {
                    v.x = fmaxf(v.x, 0.f);
                    v.y = fmaxf(v.y, 0.f);
                    v.z = fmaxf(v.z, 0.f);
                    v.w = fmaxf(v.w, 0.f);
                }
            }
            __nv_bfloat162 h0 = __float22bfloat162_rn(make_float2(v.x, v.y));
            __nv_bfloat162 h1 = __float22bfloat162_rn(make_float2(v.z, v.w));
            float2 f0 = __bfloat1622float2(h0);
            float2 f1 = __bfloat1622float2(h1);
            __nv_bfloat162 l0 =
                __float22bfloat162_rn(make_float2(v.x - f0.x, v.y - f0.y));
            __nv_bfloat162 l1 =
                __float22bfloat162_rn(make_float2(v.z - f1.x, v.w - f1.y));
            uint32_t off = SW128((uint32_t)(r * 128 + kq * 8));
            *(uint2*)(smem + A_HI + off) = make_uint2(*(uint32_t*)&h0, *(uint32_t*)&h1);
            *(uint2*)(smem + A_LO + off) = make_uint2(*(uint32_t*)&l0, *(uint32_t*)&l1);
        }
    };

    loadA(0, 0);
    if (wid == 0) {
        TC_ALLOC(sb + 0, 256);
        TC_RELINQ();
    }
    if (tid == 0) MBAR_INIT(sb + 8, 1);
    FENCE_ASYNC_SHARED();
    __syncthreads();
    uint32_t tmem;
    asm volatile("ld.shared.b32 %0, [%1];" : "=r"(tmem) : "r"(sb + 0));

    const uint32_t IDESC =
        (1u << 4) | (1u << 7) | (1u << 10) | (16u << 17) | (8u << 24);

    // ---- epilogue for one 128-row half (warps 0-3) ----
    auto epilogue = [&](int half) {
        if (wid >= 4) return;
        const int row = m0 + half * 128 + wid * 32 + lane;
        const uint32_t tbase = tmem + half * 128;
#pragma unroll
        for (int cb = 0; cb < 4; cb++) {
            uint32_t r[32];
            TC_LD_X32(r, tbase + cb * 32);
            TC_WAIT_LD();
            if (row < NN) {
#pragma unroll
                for (int t = 0; t < 8; t++) {
                    float4 v = make_float4(
                        __uint_as_float(r[4 * t + 0]), __uint_as_float(r[4 * t + 1]),
                        __uint_as_float(r[4 * t + 2]), __uint_as_float(r[4 * t + 3]));
                    int j4 = cb * 8 + t;
                    if (j4 < 16) {
                        g_hw[row * 16 + j4] = v;
                    } else {
                        int jj = (j4 - 16) * 4;
                        v.x += bias[jj + 0];
                        v.y += bias[jj + 1];
                        v.z += bias[jj + 2];
                        v.w += bias[jj + 3];
                        accOut[row * 16 + (j4 - 16)] = v;
                    }
                }
            }
        }
    };

    int w = 0;  // commit counter
#pragma unroll
    for (int half = 0; half < 2; half++) {
#pragma unroll
        for (int c = 0; c < CHUNKS; c++) {
            if (half + c > 0) {
                // wait for previous MMA set before overwriting A tiles
                mbar_wait(sb + 8, (uint32_t)((w - 1) & 1));
                loadA(half, c);
                FENCE_ASYNC_SHARED();
                __syncthreads();
            }
            if (wid == 0 && elect_one()) {
                uint64_t ah = make_desc(sb + A_HI), al = make_desc(sb + A_LO);
                uint64_t bh = make_desc(sb + B_HI + c * 16384);
                uint64_t bl = make_desc(sb + B_LO + c * 16384);
                uint32_t d = tmem + half * 128;
#pragma unroll
                for (int s = 0; s < 4; s++)
                    mma_f16_ss(d, ah + 2 * s, bh + 2 * s, IDESC, !(c == 0 && s == 0));
#pragma unroll
                for (int s = 0; s < 4; s++)
                    mma_f16_ss(d, ah + 2 * s, bl + 2 * s, IDESC, true);
#pragma unroll
                for (int s = 0; s < 4; s++)
                    mma_f16_ss(d, al + 2 * s, bh + 2 * s, IDESC, true);
                TC_COMMIT(sb + 8);
            }
            w++;
            if (half == 1 && c == 0) {
                // D0 is final (last half-0 commit already waited); overlap its
                // epilogue with half-1 tensor work.
                TC_FENCE_AFTER();
                epilogue(0);
            }
        }
    }
    mbar_wait(sb + 8, (uint32_t)((w - 1) & 1));
    TC_FENCE_AFTER();
    epilogue(1);
    TC_FENCE_BEFORE();
    __syncthreads();
    if (tid == 0) MBAR_INVAL(sb + 8);
    if (wid == 0) TC_DEALLOC(tmem, 256);

#else
    // ======== FMA fallback (plain sm_103 target) — round-5 proven path ========
    float* a_s = (float*)smem;                    // [32][68]
    float4* b_s = (float4*)(smem + 32 * 68 * 4);  // [32][32]
    const float4* wc4 = (const float4*)g_wc[layer];
    const int ty = wid;

    for (int half = 0; half < 4; half++) {
        const int hm0 = m0 + half * 64;
        unsigned long long acc[8][2];
#pragma unroll
        for (int i = 0; i < 8; i++) { acc[i][0] = 0ull; acc[i][1] = 0ull; }

        for (int k0 = 0; k0 < IN_DIM; k0 += 32) {
#pragma unroll
            for (int t = 0; t < 2; t++) {
                int idx = t * 256 + tid;
                int r = idx >> 3;
                int kq = idx & 7;
                int row = hm0 + r;
                float4 v = make_float4(0.f, 0.f, 0.f, 0.f);
                if (row < NN) {
                    v = *(const float4*)(h + (size_t)row * IN_DIM + k0 + kq * 4);
                    if (RELU) {
                        v.x = fmaxf(v.x, 0.f);
                        v.y = fmaxf(v.y, 0.f);
                        v.z = fmaxf(v.z, 0.f);
                        v.w = fmaxf(v.w, 0.f);
                    }
                }
                a_s[(kq * 4 + 0) * 68 + r] = v.x;
                a_s[(kq * 4 + 1) * 68 + r] = v.y;
                a_s[(kq * 4 + 2) * 68 + r] = v.z;
                a_s[(kq * 4 + 3) * 68 + r] = v.w;
            }
#pragma unroll
            for (int t = 0; t < 4; t++) {
                int idx = t * 256 + tid;
                b_s[idx] = wc4[(size_t)(k0 + (idx >> 5)) * 32 + (idx & 31)];
            }
            __syncthreads();

#pragma unroll
            for (int k = 0; k < 32; k++) {
                float4 b4 = b_s[k * 32 + lane];
                unsigned long long b01 = pack2(b4.x, b4.y);
                unsigned long long b23 = pack2(b4.z, b4.w);
                float4 a0 = *(const float4*)&a_s[k * 68 + ty * 8];
                float4 a1 = *(const float4*)&a_s[k * 68 + ty * 8 + 4];
                unsigned long long a2;
                a2 = pack2(a0.x, a0.x); fma2(acc[0][0], a2, b01); fma2(acc[0][1], a2, b23);
                a2 = pack2(a0.y, a0.y); fma2(acc[1][0], a2, b01); fma2(acc[1][1], a2, b23);
                a2 = pack2(a0.z, a0.z); fma2(acc[2][0], a2, b01); fma2(acc[2][1], a2, b23);
                a2 = pack2(a0.w, a0.w); fma2(acc[3][0], a2, b01); fma2(acc[3][1], a2, b23);
                a2 = pack2(a1.x, a1.x); fma2(acc[4][0], a2, b01); fma2(acc[4][1], a2, b23);
                a2 = pack2(a1.y, a1.y); fma2(acc[5][0], a2, b01); fma2(acc[5][1], a2, b23);
                a2 = pack2(a1.z, a1.z); fma2(acc[6][0], a2, b01); fma2(acc[6][1], a2, b23);
                a2 = pack2(a1.w, a1.w); fma2(acc[7][0], a2, b01); fma2(acc[7][1], a2, b23);
            }
            __syncthreads();
        }

#pragma unroll
        for (int i = 0; i < 8; i++) {
            int row = hm0 + ty * 8 + i;
            if (row < NN) {
                float2 lo = unpack2(acc[i][0]);
                float2 hi = unpack2(acc[i][1]);
                float4 v = make_float4(lo.x, lo.y, hi.x, hi.y);
                if (lane < 16) {
                    g_hw[row * 16 + lane] = v;
                } else {
                    int jj = (lane - 16) * 4;
                    v.x += bias[jj + 0];
                    v.y += bias[jj + 1];
                    v.z += bias[jj + 2];
                    v.w += bias[jj + 3];
                    accOut[row * 16 + (lane - 16)] = v;
                }
            }
        }
        __syncthreads();
    }
#endif
}

// ---------------- scatter: acc[src] += hw[dst] over compacted bucket
// thread-per-(edge,chunk), batched grid-stride unroll-4 (round-9/11 proven)
__global__ __launch_bounds__(256) void scatter_kernel(int rel, int dst_sel) {
    float4* __restrict__ acc = dst_sel ? g_accB : g_accA;
    const int2* __restrict__ bk = g_bucket[rel];
    const int n16 = g_cnt[rel] << 4;
    const int T = gridDim.x * blockDim.x;
    int id0 = blockIdx.x * blockDim.x + threadIdx.x;
    for (int base = id0; base < n16; base += 4 * T) {
        int ids[4];
        int2 p[4];
        bool ok[4];
#pragma unroll
        for (int u = 0; u < 4; u++) {
            ids[u] = base + u * T;
            ok[u] = ids[u] < n16;
            p[u] = ok[u] ? bk[ids[u] >> 4] : make_int2(0, 0);
        }
        float4 v[4];
#pragma unroll
        for (int u = 0; u < 4; u++)
            v[u] = ok[u] ? g_hw[p[u].y * 16 + (ids[u] & 15)]
                         : make_float4(0.f, 0.f, 0.f, 0.f);
#pragma unroll
        for (int u = 0; u < 4; u++) {
            if (ok[u]) {
                float* dp = (float*)acc + (size_t)p[u].x * 64 + (ids[u] & 15) * 4;
                asm volatile("red.global.add.v4.f32 [%0], {%1,%2,%3,%4};" ::"l"(dp),
                             "f"(v[u].x), "f"(v[u].y), "f"(v[u].z), "f"(v[u].w)
                             : "memory");
            }
        }
    }
}

// ---------------- final relu (+ end-of-launch g_cnt reset for next replay)
__global__ __launch_bounds__(256) void relu_kernel(float* __restrict__ out) {
    int i = blockIdx.x * blockDim.x + threadIdx.x;
    if (i < NN * 16) {
        float4 v = g_accA[i];
        v.x = fmaxf(v.x, 0.f);
        v.y = fmaxf(v.y, 0.f);
        v.z = fmaxf(v.z, 0.f);
        v.w = fmaxf(v.w, 0.f);
        ((float4*)out)[i] = v;
    }
    if (blockIdx.x == 0 && threadIdx.x < 3) g_cnt[threadIdx.x] = 0;
}

extern "C" void kernel_launch(void* const* d_in, const int* in_sizes, int n_in,
                              void* d_out, int out_size) {
    const float* x = (const float*)d_in[0];
    const int* ei = (const int*)d_in[1];
    const int* et = (const int*)d_in[2];
    float* out = (float*)d_out;

    const float* W[18];
    for (int i = 0; i < 18; i++) W[i] = (const float*)d_in[3 + i];

    const int SMEM_L0 = 1024 + 32768 + 65536;   // 99328 (CHUNKS=2)
    const int SMEM_L12 = 1024 + 32768 + 32768;  // 66560 (CHUNKS=1)
    cudaFuncSetAttribute(gemm_tc_kernel<128, false>,
                         cudaFuncAttributeMaxDynamicSharedMemorySize, SMEM_L0);
    cudaFuncSetAttribute(gemm_tc_kernel<64, true>,
                         cudaFuncAttributeMaxDynamicSharedMemorySize, SMEM_L12);

    const int GEMM_GRID = (NN + 255) / 256;  // 391
    const int SCAT_GRID = 2048;
    const int RELU_GRID = (NN * 16 + 255) / 256;
    const int BUCK_GRID = (NE + 255) / 256;  // 3907

    // merged prep + bucket: blocks [0,192) prep, [192, 192+BUCK) bucket
    prep_bucket_kernel<<<192 + BUCK_GRID, 256>>>(
        ei, et, W[0], W[1], W[2], W[3], W[4], W[5], W[6], W[7], W[8], W[9], W[10],
        W[11], W[12], W[13], W[14], W[15], W[16], W[17]);

    // Layer 0: x -> accA
    gemm_tc_kernel<128, false><<<GEMM_GRID, 256, SMEM_L0>>>(x, 0, 0, 0);
    scatter_kernel<<<SCAT_GRID, 256>>>(0, 0);
    // Layer 1: relu(accA) -> accB
    gemm_tc_kernel<64, true><<<GEMM_GRID, 256, SMEM_L12>>>(x, 1, 1, 1);
    scatter_kernel<<<SCAT_GRID, 256>>>(1, 1);
    // Layer 2: relu(accB) -> accA
    gemm_tc_kernel<64, true><<<GEMM_GRID, 256, SMEM_L12>>>(x, 2, 0, 2);
    scatter_kernel<<<SCAT_GRID, 256>>>(2, 0);

    relu_kernel<<<RELU_GRID, 256>>>(out);
}